// round 1
// baseline (speedup 1.0000x reference)
#include <cuda_runtime.h>
#include <cuda_bf16.h>
#include <math.h>

#define N_NODES   100000
#define N_EDGES   1600000
#define NUM_GRAPHS 64
#define IN_CH     128
#define HID       64
#define NUM_CLASSES 10

// ---------------- scratch (static device globals; no allocation) ----------------
__device__ int   g_cnt[N_NODES];          // in-degree (without self loop)
__device__ int   g_fill[N_NODES];         // CSR fill cursor
__device__ float g_dinv[N_NODES];         // 1/sqrt(deg)
__device__ int   g_rowptr[N_NODES + 1];
__device__ int   g_col[N_EDGES];          // CSR: src node per edge (grouped by dst)
__device__ float g_enorm[N_EDGES];        // CSR: dinv[src]*dinv[dst]
__device__ float g_t[(size_t)N_NODES * HID];   // GEMM output buffer (also holds N x 10)
__device__ float g_h[(size_t)N_NODES * HID];   // propagation output buffer
__device__ float g_pool[NUM_GRAPHS * NUM_CLASSES];
__device__ float g_pcnt[NUM_GRAPHS];

// ---------------- init ----------------
__global__ void zero_kernel() {
    int i = blockIdx.x * blockDim.x + threadIdx.x;
    if (i < N_NODES) { g_cnt[i] = 0; g_fill[i] = 0; }
    if (i < NUM_GRAPHS * NUM_CLASSES) g_pool[i] = 0.f;
    if (i < NUM_GRAPHS) g_pcnt[i] = 0.f;
}

// ---------------- degree count ----------------
__global__ void count_kernel(const int* __restrict__ ei) {
    int e = blockIdx.x * blockDim.x + threadIdx.x;
    if (e < N_EDGES) {
        int d = ei[N_EDGES + e];   // dst row of edge_index
        atomicAdd(&g_cnt[d], 1);
    }
}

__global__ void dinv_kernel() {
    int v = blockIdx.x * blockDim.x + threadIdx.x;
    if (v < N_NODES) {
        float deg = (float)(g_cnt[v] + 1);  // +1 self loop
        g_dinv[v] = rsqrtf(deg);
    }
}

// ---------------- exclusive scan (single block, 512 threads x 8 items) ----------------
__global__ void scan_kernel(int n) {
    const int T = 512, IT = 8, CH = T * IT;
    int tid = threadIdx.x, lane = tid & 31, warp = tid >> 5;
    __shared__ int wsum[16];
    __shared__ int s_total;
    int running = 0;
    for (int c0 = 0; c0 < n; c0 += CH) {
        int base = c0 + tid * IT;
        int v[IT]; int s = 0;
        #pragma unroll
        for (int i = 0; i < IT; i++) {
            int x = (base + i < n) ? g_cnt[base + i] : 0;
            s += x; v[i] = s;   // inclusive within thread
        }
        int x = s;
        #pragma unroll
        for (int off = 1; off < 32; off <<= 1) {
            int y = __shfl_up_sync(0xffffffffu, x, off);
            if (lane >= off) x += y;
        }
        if (lane == 31) wsum[warp] = x;
        __syncthreads();
        if (warp == 0 && lane < 16) {
            int w = wsum[lane];
            #pragma unroll
            for (int off = 1; off < 16; off <<= 1) {
                int y = __shfl_up_sync(0x0000ffffu, w, off);
                if (lane >= off) w += y;
            }
            wsum[lane] = w;
            if (lane == 15) s_total = w;
        }
        __syncthreads();
        int wpre = warp ? wsum[warp - 1] : 0;
        int excl = running + wpre + (x - s);
        #pragma unroll
        for (int i = 0; i < IT; i++)
            if (base + i < n) g_rowptr[base + i + 1] = excl + v[i];
        running += s_total;
        __syncthreads();
    }
    if (tid == 0) g_rowptr[0] = 0;
}

// ---------------- CSR scatter ----------------
__global__ void scatter_kernel(const int* __restrict__ ei) {
    int e = blockIdx.x * blockDim.x + threadIdx.x;
    if (e < N_EDGES) {
        int s = ei[e];
        int d = ei[N_EDGES + e];
        int pos = g_rowptr[d] + atomicAdd(&g_fill[d], 1);
        g_col[pos] = s;
        g_enorm[pos] = g_dinv[s] * g_dinv[d];
    }
}

// ---------------- GEMM: [n x K] @ [K x 64] -> [n x 64] ----------------
template <int K>
__global__ void gemm_out64(const float* __restrict__ A, const float* __restrict__ W,
                           float* __restrict__ C, int n) {
    const int NPB = 64;
    __shared__ __align__(16) float As[8][NPB];
    __shared__ __align__(16) float Ws[8][64];
    int tid = threadIdx.x;
    int n0 = blockIdx.x * NPB;
    int nl = tid >> 2;   // local node 0..63
    int cg = tid & 3;    // column group 0..3 (16 cols each)
    float4 acc[4];
    #pragma unroll
    for (int q = 0; q < 4; q++) acc[q] = make_float4(0.f, 0.f, 0.f, 0.f);

    for (int k0 = 0; k0 < K; k0 += 8) {
        #pragma unroll
        for (int i = 0; i < 2; i++) {
            int flat = tid + i * 256;
            int kk = flat & 7, nn = flat >> 3;
            int gn = n0 + nn;
            As[kk][nn] = (gn < n) ? A[(size_t)gn * K + k0 + kk] : 0.f;
        }
        #pragma unroll
        for (int i = 0; i < 2; i++) {
            int flat = tid + i * 256;
            int kk = flat >> 6, c = flat & 63;
            Ws[kk][c] = W[(k0 + kk) * 64 + c];
        }
        __syncthreads();
        #pragma unroll
        for (int kk = 0; kk < 8; kk++) {
            float a = As[kk][nl];
            const float4* w4 = reinterpret_cast<const float4*>(&Ws[kk][cg * 16]);
            #pragma unroll
            for (int q = 0; q < 4; q++) {
                float4 w = w4[q];
                acc[q].x += a * w.x; acc[q].y += a * w.y;
                acc[q].z += a * w.z; acc[q].w += a * w.w;
            }
        }
        __syncthreads();
    }
    int gn = n0 + nl;
    if (gn < n) {
        float4* out = reinterpret_cast<float4*>(C + (size_t)gn * 64 + cg * 16);
        #pragma unroll
        for (int q = 0; q < 4; q++) out[q] = acc[q];
    }
}

// ---------------- GEMM: [n x 64] @ [64 x 10] -> [n x 10] ----------------
__global__ void gemm_out10(const float* __restrict__ A, const float* __restrict__ W,
                           float* __restrict__ C, int n) {
    __shared__ float Ws[64][10];
    __shared__ float As[16][257];
    int tid = threadIdx.x;
    for (int i = tid; i < 640; i += 256) Ws[i / 10][i % 10] = W[i];
    int n0 = blockIdx.x * 256;
    float acc[10];
    #pragma unroll
    for (int c = 0; c < 10; c++) acc[c] = 0.f;

    for (int k0 = 0; k0 < 64; k0 += 16) {
        #pragma unroll
        for (int i = 0; i < 4; i++) {
            int flat4 = tid + i * 256;      // float4 units: 1024 total
            int node = flat4 >> 2;
            int kp = (flat4 & 3) * 4;
            int gn = n0 + node;
            float4 v = (gn < n)
                ? *reinterpret_cast<const float4*>(&A[(size_t)gn * 64 + k0 + kp])
                : make_float4(0.f, 0.f, 0.f, 0.f);
            As[kp][node] = v.x; As[kp + 1][node] = v.y;
            As[kp + 2][node] = v.z; As[kp + 3][node] = v.w;
        }
        __syncthreads();
        #pragma unroll
        for (int kk = 0; kk < 16; kk++) {
            float a = As[kk][tid];
            #pragma unroll
            for (int c = 0; c < 10; c++) acc[c] += a * Ws[k0 + kk][c];
        }
        __syncthreads();
    }
    int gn = n0 + tid;
    if (gn < n) {
        #pragma unroll
        for (int c = 0; c < 10; c++) C[(size_t)gn * 10 + c] = acc[c];
    }
}

// ---------------- propagation, 64 channels: warp per node ----------------
__global__ void prop64(const float* __restrict__ Hin, float* __restrict__ Hout,
                       const float* __restrict__ bias, int n, int do_relu) {
    int gtid = blockIdx.x * blockDim.x + threadIdx.x;
    int v = gtid >> 5;
    int lane = threadIdx.x & 31;
    int wl = threadIdx.x >> 5;
    __shared__ int   s_col[8][32];
    __shared__ float s_nm[8][32];
    if (v >= n) return;

    float dv = g_dinv[v];
    float selfn = dv * dv;
    float2 xv = reinterpret_cast<const float2*>(Hin + (size_t)v * 64)[lane];
    float2 acc = make_float2(selfn * xv.x, selfn * xv.y);

    int e0 = g_rowptr[v], e1 = g_rowptr[v + 1];
    for (int base = e0; base < e1; base += 32) {
        int ne = min(32, e1 - base);
        if (lane < ne) {
            s_col[wl][lane] = g_col[base + lane];
            s_nm[wl][lane]  = g_enorm[base + lane];
        }
        __syncwarp();
        #pragma unroll 4
        for (int j = 0; j < ne; j++) {
            int s = s_col[wl][j];
            float nm = s_nm[wl][j];
            float2 hh = reinterpret_cast<const float2*>(Hin + (size_t)s * 64)[lane];
            acc.x += nm * hh.x;
            acc.y += nm * hh.y;
        }
        __syncwarp();
    }
    float2 b = reinterpret_cast<const float2*>(bias)[lane];
    acc.x += b.x; acc.y += b.y;
    if (do_relu) {
        acc.x = fmaxf(acc.x, 0.f);
        acc.y = fmaxf(acc.y, 0.f);
    }
    reinterpret_cast<float2*>(Hout + (size_t)v * 64)[lane] = acc;
}

// ---------------- propagation, 10 channels: warp per node ----------------
__global__ void prop10(const float* __restrict__ Hin, float* __restrict__ Hout,
                       const float* __restrict__ bias, int n) {
    int gtid = blockIdx.x * blockDim.x + threadIdx.x;
    int v = gtid >> 5;
    int lane = threadIdx.x & 31;
    int wl = threadIdx.x >> 5;
    __shared__ int   s_col[8][32];
    __shared__ float s_nm[8][32];
    if (v >= n) return;

    float dv = g_dinv[v];
    float selfn = dv * dv;
    float acc = 0.f;
    if (lane < NUM_CLASSES) acc = selfn * Hin[(size_t)v * 10 + lane];

    int e0 = g_rowptr[v], e1 = g_rowptr[v + 1];
    for (int base = e0; base < e1; base += 32) {
        int ne = min(32, e1 - base);
        if (lane < ne) {
            s_col[wl][lane] = g_col[base + lane];
            s_nm[wl][lane]  = g_enorm[base + lane];
        }
        __syncwarp();
        for (int j = 0; j < ne; j++) {
            int s = s_col[wl][j];
            float nm = s_nm[wl][j];
            if (lane < NUM_CLASSES)
                acc += nm * Hin[(size_t)s * 10 + lane];
        }
        __syncwarp();
    }
    if (lane < NUM_CLASSES)
        Hout[(size_t)v * 10 + lane] = acc + bias[lane];
}

// ---------------- pooling (shared-mem staged) ----------------
__global__ void pool_kernel(const float* __restrict__ H, const int* __restrict__ batch, int n) {
    __shared__ float sp[NUM_GRAPHS * NUM_CLASSES];
    __shared__ float sc[NUM_GRAPHS];
    int tid = threadIdx.x;
    for (int i = tid; i < NUM_GRAPHS * NUM_CLASSES; i += 256) sp[i] = 0.f;
    if (tid < NUM_GRAPHS) sc[tid] = 0.f;
    __syncthreads();

    int node = blockIdx.x * 256 + tid;
    if (node < n) {
        int g = batch[node];
        atomicAdd(&sc[g], 1.f);
        const float* row = H + (size_t)node * 10;
        #pragma unroll
        for (int c = 0; c < 10; c++) atomicAdd(&sp[g * 10 + c], row[c]);
    }
    __syncthreads();
    for (int i = tid; i < NUM_GRAPHS * NUM_CLASSES; i += 256)
        if (sp[i] != 0.f) atomicAdd(&g_pool[i], sp[i]);
    if (tid < NUM_GRAPHS && sc[tid] != 0.f) atomicAdd(&g_pcnt[tid], sc[tid]);
}

// ---------------- final mean + log_softmax ----------------
__global__ void final_kernel(float* __restrict__ out) {
    int g = threadIdx.x;
    if (g >= NUM_GRAPHS) return;
    float inv = 1.f / fmaxf(g_pcnt[g], 1.f);
    float v[NUM_CLASSES];
    float m = -1e30f;
    #pragma unroll
    for (int c = 0; c < NUM_CLASSES; c++) {
        v[c] = g_pool[g * 10 + c] * inv;
        m = fmaxf(m, v[c]);
    }
    float ssum = 0.f;
    #pragma unroll
    for (int c = 0; c < NUM_CLASSES; c++) ssum += expf(v[c] - m);
    float lse = m + logf(ssum);
    #pragma unroll
    for (int c = 0; c < NUM_CLASSES; c++) out[g * 10 + c] = v[c] - lse;
}

// ---------------- launch ----------------
extern "C" void kernel_launch(void* const* d_in, const int* in_sizes, int n_in,
                              void* d_out, int out_size) {
    const float* x   = (const float*)d_in[0];
    const int*   ei  = (const int*)d_in[1];
    const int*   bat = (const int*)d_in[2];
    const float* W1  = (const float*)d_in[3];
    const float* b1  = (const float*)d_in[4];
    const float* W2  = (const float*)d_in[5];
    const float* b2  = (const float*)d_in[6];
    const float* W3  = (const float*)d_in[7];
    const float* b3  = (const float*)d_in[8];
    float* out = (float*)d_out;

    float* t  = nullptr; float* h = nullptr;
    cudaGetSymbolAddress((void**)&t, g_t);
    cudaGetSymbolAddress((void**)&h, g_h);

    const int TB = 256;
    int nblk  = (N_NODES + TB - 1) / TB;            // 391
    int eblk  = (N_EDGES + TB - 1) / TB;            // 6250
    int wblk  = (N_NODES * 32 + TB - 1) / TB;       // 12500 (warp per node)
    int gblk  = (N_NODES + 63) / 64;                // 1563

    zero_kernel<<<nblk, TB>>>();
    count_kernel<<<eblk, TB>>>(ei);
    dinv_kernel<<<nblk, TB>>>();
    scan_kernel<<<1, 512>>>(N_NODES);
    scatter_kernel<<<eblk, TB>>>(ei);

    // layer 1: t = x @ W1 ; h = relu(prop(t) + b1)
    gemm_out64<IN_CH><<<gblk, TB>>>(x, W1, t, N_NODES);
    prop64<<<wblk, TB>>>(t, h, b1, N_NODES, 1);

    // layer 2: t = h @ W2 ; h = relu(prop(t) + b2)
    gemm_out64<HID><<<gblk, TB>>>(h, W2, t, N_NODES);
    prop64<<<wblk, TB>>>(t, h, b2, N_NODES, 1);

    // layer 3: t = h @ W3 (N x 10) ; h = prop(t) + b3
    gemm_out10<<<nblk, TB>>>(h, W3, t, N_NODES);
    prop10<<<wblk, TB>>>(t, h, b3, N_NODES);

    // pooling + log_softmax
    pool_kernel<<<nblk, TB>>>(h, bat, N_NODES);
    final_kernel<<<1, 64>>>(out);
}

// round 2
// speedup vs baseline: 1.5400x; 1.5400x over previous
#include <cuda_runtime.h>
#include <cuda_bf16.h>
#include <math.h>

#define N_NODES   100000
#define N_EDGES   1600000
#define NUM_GRAPHS 64
#define IN_CH     128
#define HID       64
#define NUM_CLASSES 10

#define SCAN_BS   256
#define SCAN_IT   4
#define SCAN_CHUNK (SCAN_BS * SCAN_IT)                       // 1024
#define SCAN_NBLK ((N_NODES + SCAN_CHUNK - 1) / SCAN_CHUNK)  // 98

// ---------------- scratch (static device globals; no allocation) ----------------
__device__ int   g_cnt[N_NODES];
__device__ int   g_fill[N_NODES];
__device__ float g_dinv[N_NODES];
__device__ int   g_rowptr[N_NODES + 1];
__device__ int2  g_edge[N_EDGES];             // {src, float_bits(norm)} grouped by dst
__device__ int   g_bsum[SCAN_NBLK];
__device__ int   g_bbase[SCAN_NBLK];
__device__ float g_t[(size_t)N_NODES * HID];
__device__ float g_h[(size_t)N_NODES * HID];
__device__ float g_pool[NUM_GRAPHS * NUM_CLASSES];
__device__ float g_pcnt[NUM_GRAPHS];

// ---------------- degree count ----------------
__global__ void count_kernel(const int* __restrict__ ei) {
    int e = blockIdx.x * blockDim.x + threadIdx.x;
    if (e < N_EDGES) atomicAdd(&g_cnt[ei[N_EDGES + e]], 1);
}

// ---------------- pass A: per-block sums + dinv ----------------
__global__ void blocksum_dinv() {
    int b = blockIdx.x, t = threadIdx.x;
    int i0 = b * SCAN_CHUNK + t * SCAN_IT;
    int s = 0;
    #pragma unroll
    for (int i = 0; i < SCAN_IT; i++) {
        int idx = i0 + i;
        if (idx < N_NODES) {
            int c = g_cnt[idx];
            s += c;
            g_dinv[idx] = rsqrtf((float)(c + 1));   // +1 self loop
        }
    }
    #pragma unroll
    for (int off = 16; off; off >>= 1) s += __shfl_down_sync(0xffffffffu, s, off);
    __shared__ int ws[8];
    if ((t & 31) == 0) ws[t >> 5] = s;
    __syncthreads();
    if (t < 8) {
        int v = ws[t];
        #pragma unroll
        for (int off = 4; off; off >>= 1) v += __shfl_down_sync(0xffu, v, off);
        if (t == 0) g_bsum[b] = v;
    }
}

// ---------------- pass B: exclusive scan of 98 partials ----------------
__global__ void scan_partials() {
    __shared__ int sm[SCAN_NBLK];
    int t = threadIdx.x;
    if (t < SCAN_NBLK) sm[t] = g_bsum[t];
    __syncthreads();
    if (t == 0) {
        int acc = 0;
        for (int i = 0; i < SCAN_NBLK; i++) { int v = sm[i]; sm[i] = acc; acc += v; }
    }
    __syncthreads();
    if (t < SCAN_NBLK) g_bbase[t] = sm[t];
}

// ---------------- pass C: write rowptr ----------------
__global__ void write_rowptr() {
    int b = blockIdx.x, t = threadIdx.x;
    int lane = t & 31, warp = t >> 5;
    int i0 = b * SCAN_CHUNK + t * SCAN_IT;
    int v[SCAN_IT]; int s = 0;
    #pragma unroll
    for (int i = 0; i < SCAN_IT; i++) {
        int idx = i0 + i;
        int c = (idx < N_NODES) ? g_cnt[idx] : 0;
        s += c; v[i] = s;
    }
    int x = s;
    #pragma unroll
    for (int off = 1; off < 32; off <<= 1) {
        int y = __shfl_up_sync(0xffffffffu, x, off);
        if (lane >= off) x += y;
    }
    __shared__ int ws[8];
    if (lane == 31) ws[warp] = x;
    __syncthreads();
    if (t == 0) { int a = 0; for (int w = 0; w < 8; w++) { int y = ws[w]; ws[w] = a; a += y; } }
    __syncthreads();
    int excl = g_bbase[b] + ws[warp] + (x - s);
    #pragma unroll
    for (int i = 0; i < SCAN_IT; i++) {
        int idx = i0 + i;
        if (idx < N_NODES) g_rowptr[idx + 1] = excl + v[i];
    }
    if (b == 0 && t == 0) g_rowptr[0] = 0;
}

// ---------------- CSR scatter (packed int2) ----------------
__global__ void scatter_kernel(const int* __restrict__ ei) {
    int e = blockIdx.x * blockDim.x + threadIdx.x;
    if (e < N_EDGES) {
        int s = ei[e];
        int d = ei[N_EDGES + e];
        int pos = g_rowptr[d] + atomicAdd(&g_fill[d], 1);
        g_edge[pos] = make_int2(s, __float_as_int(g_dinv[s] * g_dinv[d]));
    }
}

// ---------------- GEMM: [n x K] @ [K x 64] -> [n x 64], 128 nodes/block ----------------
template <int K>
__global__ void gemm_out64(const float* __restrict__ A, const float* __restrict__ W,
                           float* __restrict__ C, int n) {
    const int NPB = 128;
    __shared__ __align__(16) float As[8][NPB];
    __shared__ __align__(16) float Ws[8][64];
    int tid = threadIdx.x;
    int n0 = blockIdx.x * NPB;
    int nl = tid >> 2;   // 0..63 : handles nodes nl and nl+64
    int cg = tid & 3;    // column group (16 cols)
    float4 acc0[4], acc1[4];
    #pragma unroll
    for (int q = 0; q < 4; q++) {
        acc0[q] = make_float4(0.f, 0.f, 0.f, 0.f);
        acc1[q] = make_float4(0.f, 0.f, 0.f, 0.f);
    }

    for (int k0 = 0; k0 < K; k0 += 8) {
        #pragma unroll
        for (int i = 0; i < 4; i++) {
            int flat = tid + i * 256;           // 1024 elements
            int kk = flat & 7, nn = flat >> 3;
            int gn = n0 + nn;
            As[kk][nn] = (gn < n) ? A[(size_t)gn * K + k0 + kk] : 0.f;
        }
        #pragma unroll
        for (int i = 0; i < 2; i++) {
            int flat = tid + i * 256;
            int kk = flat >> 6, c = flat & 63;
            Ws[kk][c] = W[(k0 + kk) * 64 + c];
        }
        __syncthreads();
        #pragma unroll
        for (int kk = 0; kk < 8; kk++) {
            float a0 = As[kk][nl];
            float a1 = As[kk][nl + 64];
            const float4* w4 = reinterpret_cast<const float4*>(&Ws[kk][cg * 16]);
            #pragma unroll
            for (int q = 0; q < 4; q++) {
                float4 w = w4[q];
                acc0[q].x += a0 * w.x; acc0[q].y += a0 * w.y;
                acc0[q].z += a0 * w.z; acc0[q].w += a0 * w.w;
                acc1[q].x += a1 * w.x; acc1[q].y += a1 * w.y;
                acc1[q].z += a1 * w.z; acc1[q].w += a1 * w.w;
            }
        }
        __syncthreads();
    }
    int gn0 = n0 + nl, gn1 = n0 + nl + 64;
    if (gn0 < n) {
        float4* out = reinterpret_cast<float4*>(C + (size_t)gn0 * 64 + cg * 16);
        #pragma unroll
        for (int q = 0; q < 4; q++) out[q] = acc0[q];
    }
    if (gn1 < n) {
        float4* out = reinterpret_cast<float4*>(C + (size_t)gn1 * 64 + cg * 16);
        #pragma unroll
        for (int q = 0; q < 4; q++) out[q] = acc1[q];
    }
}

// ---------------- GEMM: [n x 64] @ [64 x 10] -> [n x 10] ----------------
__global__ void gemm_out10(const float* __restrict__ A, const float* __restrict__ W,
                           float* __restrict__ C, int n) {
    __shared__ float Ws[64][10];
    __shared__ float As[16][257];
    int tid = threadIdx.x;
    for (int i = tid; i < 640; i += 256) Ws[i / 10][i % 10] = W[i];
    int n0 = blockIdx.x * 256;
    float acc[10];
    #pragma unroll
    for (int c = 0; c < 10; c++) acc[c] = 0.f;

    for (int k0 = 0; k0 < 64; k0 += 16) {
        #pragma unroll
        for (int i = 0; i < 4; i++) {
            int flat4 = tid + i * 256;
            int node = flat4 >> 2;
            int kp = (flat4 & 3) * 4;
            int gn = n0 + node;
            float4 v = (gn < n)
                ? *reinterpret_cast<const float4*>(&A[(size_t)gn * 64 + k0 + kp])
                : make_float4(0.f, 0.f, 0.f, 0.f);
            As[kp][node] = v.x; As[kp + 1][node] = v.y;
            As[kp + 2][node] = v.z; As[kp + 3][node] = v.w;
        }
        __syncthreads();
        #pragma unroll
        for (int kk = 0; kk < 16; kk++) {
            float a = As[kk][tid];
            #pragma unroll
            for (int c = 0; c < 10; c++) acc[c] += a * Ws[k0 + kk][c];
        }
        __syncthreads();
    }
    int gn = n0 + tid;
    if (gn < n) {
        #pragma unroll
        for (int c = 0; c < 10; c++) C[(size_t)gn * 10 + c] = acc[c];
    }
}

// ---------------- propagation, 64 channels: warp per node ----------------
__global__ void prop64(const float* __restrict__ Hin, float* __restrict__ Hout,
                       const float* __restrict__ bias, int n, int do_relu) {
    int gtid = blockIdx.x * blockDim.x + threadIdx.x;
    int v = gtid >> 5;
    int lane = threadIdx.x & 31;
    int wl = threadIdx.x >> 5;
    __shared__ int2 s_e[8][32];
    if (v >= n) return;

    float dv = g_dinv[v];
    float selfn = dv * dv;
    float2 xv = reinterpret_cast<const float2*>(Hin + (size_t)v * 64)[lane];
    float2 acc = make_float2(selfn * xv.x, selfn * xv.y);

    int e0 = g_rowptr[v], e1 = g_rowptr[v + 1];
    for (int base = e0; base < e1; base += 32) {
        int ne = min(32, e1 - base);
        if (lane < ne) s_e[wl][lane] = g_edge[base + lane];
        __syncwarp();
        #pragma unroll 4
        for (int j = 0; j < ne; j++) {
            int2 e = s_e[wl][j];
            float nm = __int_as_float(e.y);
            float2 hh = reinterpret_cast<const float2*>(Hin + (size_t)e.x * 64)[lane];
            acc.x += nm * hh.x;
            acc.y += nm * hh.y;
        }
        __syncwarp();
    }
    float2 b = reinterpret_cast<const float2*>(bias)[lane];
    acc.x += b.x; acc.y += b.y;
    if (do_relu) {
        acc.x = fmaxf(acc.x, 0.f);
        acc.y = fmaxf(acc.y, 0.f);
    }
    reinterpret_cast<float2*>(Hout + (size_t)v * 64)[lane] = acc;
}

// ---------------- propagation, 10 channels: warp per node ----------------
__global__ void prop10(const float* __restrict__ Hin, float* __restrict__ Hout,
                       const float* __restrict__ bias, int n) {
    int gtid = blockIdx.x * blockDim.x + threadIdx.x;
    int v = gtid >> 5;
    int lane = threadIdx.x & 31;
    int wl = threadIdx.x >> 5;
    __shared__ int2 s_e[8][32];
    if (v >= n) return;

    float dv = g_dinv[v];
    float selfn = dv * dv;
    float acc = 0.f;
    if (lane < NUM_CLASSES) acc = selfn * Hin[(size_t)v * 10 + lane];

    int e0 = g_rowptr[v], e1 = g_rowptr[v + 1];
    for (int base = e0; base < e1; base += 32) {
        int ne = min(32, e1 - base);
        if (lane < ne) s_e[wl][lane] = g_edge[base + lane];
        __syncwarp();
        for (int j = 0; j < ne; j++) {
            int2 e = s_e[wl][j];
            float nm = __int_as_float(e.y);
            if (lane < NUM_CLASSES)
                acc += nm * Hin[(size_t)e.x * 10 + lane];
        }
        __syncwarp();
    }
    if (lane < NUM_CLASSES)
        Hout[(size_t)v * 10 + lane] = acc + bias[lane];
}

// ---------------- pooling (shared-mem staged) ----------------
__global__ void pool_kernel(const float* __restrict__ H, const int* __restrict__ batch, int n) {
    __shared__ float sp[NUM_GRAPHS * NUM_CLASSES];
    __shared__ float sc[NUM_GRAPHS];
    int tid = threadIdx.x;
    for (int i = tid; i < NUM_GRAPHS * NUM_CLASSES; i += 256) sp[i] = 0.f;
    if (tid < NUM_GRAPHS) sc[tid] = 0.f;
    __syncthreads();

    int node = blockIdx.x * 256 + tid;
    if (node < n) {
        int g = batch[node];
        atomicAdd(&sc[g], 1.f);
        const float* row = H + (size_t)node * 10;
        #pragma unroll
        for (int c = 0; c < 10; c++) atomicAdd(&sp[g * 10 + c], row[c]);
    }
    __syncthreads();
    for (int i = tid; i < NUM_GRAPHS * NUM_CLASSES; i += 256)
        if (sp[i] != 0.f) atomicAdd(&g_pool[i], sp[i]);
    if (tid < NUM_GRAPHS && sc[tid] != 0.f) atomicAdd(&g_pcnt[tid], sc[tid]);
}

// ---------------- final mean + log_softmax ----------------
__global__ void final_kernel(float* __restrict__ out) {
    int g = threadIdx.x;
    if (g >= NUM_GRAPHS) return;
    float inv = 1.f / fmaxf(g_pcnt[g], 1.f);
    float v[NUM_CLASSES];
    float m = -1e30f;
    #pragma unroll
    for (int c = 0; c < NUM_CLASSES; c++) {
        v[c] = g_pool[g * 10 + c] * inv;
        m = fmaxf(m, v[c]);
    }
    float ssum = 0.f;
    #pragma unroll
    for (int c = 0; c < NUM_CLASSES; c++) ssum += expf(v[c] - m);
    float lse = m + logf(ssum);
    #pragma unroll
    for (int c = 0; c < NUM_CLASSES; c++) out[g * 10 + c] = v[c] - lse;
}

// ---------------- launch ----------------
extern "C" void kernel_launch(void* const* d_in, const int* in_sizes, int n_in,
                              void* d_out, int out_size) {
    const float* x   = (const float*)d_in[0];
    const int*   ei  = (const int*)d_in[1];
    const int*   bat = (const int*)d_in[2];
    const float* W1  = (const float*)d_in[3];
    const float* b1  = (const float*)d_in[4];
    const float* W2  = (const float*)d_in[5];
    const float* b2  = (const float*)d_in[6];
    const float* W3  = (const float*)d_in[7];
    const float* b3  = (const float*)d_in[8];
    float* out = (float*)d_out;

    float* t = nullptr; float* h = nullptr;
    void* p_cnt = nullptr; void* p_fill = nullptr; void* p_pool = nullptr; void* p_pcnt = nullptr;
    cudaGetSymbolAddress((void**)&t, g_t);
    cudaGetSymbolAddress((void**)&h, g_h);
    cudaGetSymbolAddress(&p_cnt, g_cnt);
    cudaGetSymbolAddress(&p_fill, g_fill);
    cudaGetSymbolAddress(&p_pool, g_pool);
    cudaGetSymbolAddress(&p_pcnt, g_pcnt);

    // one-time host-side resources (created on the pre-capture correctness call)
    static cudaStream_t s2 = nullptr;
    static cudaEvent_t evFork = nullptr, evJoin = nullptr;
    if (s2 == nullptr) {
        cudaStreamCreateWithFlags(&s2, cudaStreamNonBlocking);
        cudaEventCreateWithFlags(&evFork, cudaEventDisableTiming);
        cudaEventCreateWithFlags(&evJoin, cudaEventDisableTiming);
    }

    const int TB = 256;
    int nblk  = (N_NODES + TB - 1) / TB;
    int eblk  = (N_EDGES + TB - 1) / TB;
    int wblk  = (N_NODES * 32 + TB - 1) / TB;
    int gblk  = (N_NODES + 127) / 128;

    // ---- fork: preprocessing on s2, GEMM-1 on main ----
    cudaEventRecord(evFork, 0);
    cudaStreamWaitEvent(s2, evFork, 0);

    cudaMemsetAsync(p_cnt,  0, N_NODES * sizeof(int), s2);
    cudaMemsetAsync(p_fill, 0, N_NODES * sizeof(int), s2);
    cudaMemsetAsync(p_pool, 0, NUM_GRAPHS * NUM_CLASSES * sizeof(float), s2);
    cudaMemsetAsync(p_pcnt, 0, NUM_GRAPHS * sizeof(float), s2);
    count_kernel<<<eblk, TB, 0, s2>>>(ei);
    blocksum_dinv<<<SCAN_NBLK, SCAN_BS, 0, s2>>>();
    scan_partials<<<1, 128, 0, s2>>>();
    write_rowptr<<<SCAN_NBLK, SCAN_BS, 0, s2>>>();
    scatter_kernel<<<eblk, TB, 0, s2>>>(ei);
    cudaEventRecord(evJoin, s2);

    // main stream: x @ W1 (independent of graph structure)
    gemm_out64<IN_CH><<<gblk, TB>>>(x, W1, t, N_NODES);

    // ---- join ----
    cudaStreamWaitEvent(0, evJoin, 0);

    // layer 1 propagation
    prop64<<<wblk, TB>>>(t, h, b1, N_NODES, 1);

    // layer 2
    gemm_out64<HID><<<gblk, TB>>>(h, W2, t, N_NODES);
    prop64<<<wblk, TB>>>(t, h, b2, N_NODES, 1);

    // layer 3
    gemm_out10<<<nblk, TB>>>(h, W3, t, N_NODES);
    prop10<<<wblk, TB>>>(t, h, b3, N_NODES);

    // pooling + log_softmax
    pool_kernel<<<nblk, TB>>>(h, bat, N_NODES);
    final_kernel<<<1, 64>>>(out);
}

// round 3
// speedup vs baseline: 1.8256x; 1.1854x over previous
#include <cuda_runtime.h>
#include <cuda_fp16.h>
#include <math.h>
#include <mma.h>

using namespace nvcuda;

#define N_NODES   100000
#define N_EDGES   1600000
#define NUM_GRAPHS 64
#define IN_CH     128
#define HID       64
#define NUM_CLASSES 10

#define SCAN_BS   256
#define SCAN_IT   4
#define SCAN_CHUNK (SCAN_BS * SCAN_IT)
#define SCAN_NBLK ((N_NODES + SCAN_CHUNK - 1) / SCAN_CHUNK)  // 98

// ---------------- scratch ----------------
__device__ int   g_cnt[N_NODES];
__device__ int   g_fill[N_NODES];
__device__ float g_dinv[N_NODES];
__device__ int   g_rowptr[N_NODES + 1];
__device__ int2  g_edge[N_EDGES];
__device__ int   g_bsum[SCAN_NBLK];
__device__ int   g_bbase[SCAN_NBLK];
__device__ __align__(128) __half g_th[(size_t)N_NODES * HID];   // fp16 GEMM outputs (prop input)
__device__ __align__(128) float  g_h[(size_t)N_NODES * HID];    // fp32 prop outputs (GEMM input)
__device__ float g_t10[(size_t)N_NODES * NUM_CLASSES];
__device__ float g_pool[NUM_GRAPHS * NUM_CLASSES];
__device__ float g_pcnt[NUM_GRAPHS];

// ---------------- degree count ----------------
__global__ void count_kernel(const int* __restrict__ ei) {
    int e = blockIdx.x * blockDim.x + threadIdx.x;
    if (e < N_EDGES) atomicAdd(&g_cnt[ei[N_EDGES + e]], 1);
}

// ---------------- pass A: per-block sums + dinv ----------------
__global__ void blocksum_dinv() {
    int b = blockIdx.x, t = threadIdx.x;
    int i0 = b * SCAN_CHUNK + t * SCAN_IT;
    int s = 0;
    #pragma unroll
    for (int i = 0; i < SCAN_IT; i++) {
        int idx = i0 + i;
        if (idx < N_NODES) {
            int c = g_cnt[idx];
            s += c;
            g_dinv[idx] = rsqrtf((float)(c + 1));
        }
    }
    #pragma unroll
    for (int off = 16; off; off >>= 1) s += __shfl_down_sync(0xffffffffu, s, off);
    __shared__ int ws[8];
    if ((t & 31) == 0) ws[t >> 5] = s;
    __syncthreads();
    if (t < 8) {
        int v = ws[t];
        #pragma unroll
        for (int off = 4; off; off >>= 1) v += __shfl_down_sync(0xffu, v, off);
        if (t == 0) g_bsum[b] = v;
    }
}

// ---------------- pass B ----------------
__global__ void scan_partials() {
    __shared__ int sm[SCAN_NBLK];
    int t = threadIdx.x;
    if (t < SCAN_NBLK) sm[t] = g_bsum[t];
    __syncthreads();
    if (t == 0) {
        int acc = 0;
        for (int i = 0; i < SCAN_NBLK; i++) { int v = sm[i]; sm[i] = acc; acc += v; }
    }
    __syncthreads();
    if (t < SCAN_NBLK) g_bbase[t] = sm[t];
}

// ---------------- pass C ----------------
__global__ void write_rowptr() {
    int b = blockIdx.x, t = threadIdx.x;
    int lane = t & 31, warp = t >> 5;
    int i0 = b * SCAN_CHUNK + t * SCAN_IT;
    int v[SCAN_IT]; int s = 0;
    #pragma unroll
    for (int i = 0; i < SCAN_IT; i++) {
        int idx = i0 + i;
        int c = (idx < N_NODES) ? g_cnt[idx] : 0;
        s += c; v[i] = s;
    }
    int x = s;
    #pragma unroll
    for (int off = 1; off < 32; off <<= 1) {
        int y = __shfl_up_sync(0xffffffffu, x, off);
        if (lane >= off) x += y;
    }
    __shared__ int ws[8];
    if (lane == 31) ws[warp] = x;
    __syncthreads();
    if (t == 0) { int a = 0; for (int w = 0; w < 8; w++) { int y = ws[w]; ws[w] = a; a += y; } }
    __syncthreads();
    int excl = g_bbase[b] + ws[warp] + (x - s);
    #pragma unroll
    for (int i = 0; i < SCAN_IT; i++) {
        int idx = i0 + i;
        if (idx < N_NODES) g_rowptr[idx + 1] = excl + v[i];
    }
    if (b == 0 && t == 0) g_rowptr[0] = 0;
}

// ---------------- CSR scatter ----------------
__global__ void scatter_kernel(const int* __restrict__ ei) {
    int e = blockIdx.x * blockDim.x + threadIdx.x;
    if (e < N_EDGES) {
        int s = ei[e];
        int d = ei[N_EDGES + e];
        int pos = g_rowptr[d] + atomicAdd(&g_fill[d], 1);
        g_edge[pos] = make_int2(s, __float_as_int(g_dinv[s] * g_dinv[d]));
    }
}

// ---------------- tf32 tensor-core GEMM: [n x K] @ [K x 64] -> half [n x 64] ----------------
// block: 256 threads = 8 warps (4 Mwarps x 2 Nwarps), block tile 128x64, warp tile 32x32
template <int K>
__global__ void gemm64_tc(const float* __restrict__ A, const float* __restrict__ W,
                          __half* __restrict__ C, int n) {
    extern __shared__ float sm[];
    float (*As)[40] = reinterpret_cast<float(*)[40]>(sm);   // 128 x 32 (+pad)
    int tid = threadIdx.x, wid = tid >> 5, lane = tid & 31;
    int wm = wid >> 1, wn = wid & 1;
    int n0 = blockIdx.x * 128;

    wmma::fragment<wmma::accumulator, 16, 16, 8, float> cf[2][2];
    #pragma unroll
    for (int mm = 0; mm < 2; mm++)
        #pragma unroll
        for (int nn = 0; nn < 2; nn++)
            wmma::fill_fragment(cf[mm][nn], 0.0f);

    for (int k0 = 0; k0 < K; k0 += 32) {
        // stage A chunk: 128 rows x 32 cols (tf32-rounded)
        #pragma unroll
        for (int i = 0; i < 4; i++) {
            int f4 = tid + i * 256;       // 1024 float4 units
            int r  = f4 >> 3;
            int c4 = (f4 & 7) * 4;
            int gr = n0 + r;
            float4 v = (gr < n)
                ? *reinterpret_cast<const float4*>(A + (size_t)gr * K + k0 + c4)
                : make_float4(0.f, 0.f, 0.f, 0.f);
            As[r][c4 + 0] = wmma::__float_to_tf32(v.x);
            As[r][c4 + 1] = wmma::__float_to_tf32(v.y);
            As[r][c4 + 2] = wmma::__float_to_tf32(v.z);
            As[r][c4 + 3] = wmma::__float_to_tf32(v.w);
        }
        __syncthreads();
        #pragma unroll
        for (int ks = 0; ks < 4; ks++) {
            wmma::fragment<wmma::matrix_b, 16, 16, 8, wmma::precision::tf32, wmma::row_major> bf[2];
            #pragma unroll
            for (int nn = 0; nn < 2; nn++) {
                wmma::load_matrix_sync(bf[nn], W + (k0 + ks * 8) * 64 + wn * 32 + nn * 16, 64);
                #pragma unroll
                for (int t = 0; t < bf[nn].num_elements; t++)
                    bf[nn].x[t] = wmma::__float_to_tf32(bf[nn].x[t]);
            }
            wmma::fragment<wmma::matrix_a, 16, 16, 8, wmma::precision::tf32, wmma::row_major> af[2];
            #pragma unroll
            for (int mm = 0; mm < 2; mm++)
                wmma::load_matrix_sync(af[mm], &As[wm * 32 + mm * 16][ks * 8], 40);
            #pragma unroll
            for (int mm = 0; mm < 2; mm++)
                #pragma unroll
                for (int nn = 0; nn < 2; nn++)
                    wmma::mma_sync(cf[mm][nn], af[mm], bf[nn], cf[mm][nn]);
        }
        __syncthreads();
    }

    // store via smem staging (reuse sm): per-warp 32x36 region
    float* Cs = sm + wid * (32 * 36);
    #pragma unroll
    for (int mm = 0; mm < 2; mm++)
        #pragma unroll
        for (int nn = 0; nn < 2; nn++)
            wmma::store_matrix_sync(Cs + mm * 16 * 36 + nn * 16, cf[mm][nn], 36, wmma::mem_row_major);
    __syncwarp();

    int gr = n0 + wm * 32 + lane;
    if (gr < n) {
        __half2* dst = reinterpret_cast<__half2*>(C + (size_t)gr * 64 + wn * 32);
        const float* src = Cs + lane * 36;
        #pragma unroll
        for (int cc = 0; cc < 16; cc++)
            dst[cc] = __floats2half2_rn(src[cc * 2], src[cc * 2 + 1]);
    }
}

// ---------------- GEMM: [n x 64] @ [64 x 10] -> [n x 10] fp32 ----------------
__global__ void gemm_out10(const float* __restrict__ A, const float* __restrict__ W,
                           float* __restrict__ C, int n) {
    __shared__ float Ws[64][10];
    __shared__ float As[16][257];
    int tid = threadIdx.x;
    for (int i = tid; i < 640; i += 256) Ws[i / 10][i % 10] = W[i];
    int n0 = blockIdx.x * 256;
    float acc[10];
    #pragma unroll
    for (int c = 0; c < 10; c++) acc[c] = 0.f;

    for (int k0 = 0; k0 < 64; k0 += 16) {
        #pragma unroll
        for (int i = 0; i < 4; i++) {
            int flat4 = tid + i * 256;
            int node = flat4 >> 2;
            int kp = (flat4 & 3) * 4;
            int gn = n0 + node;
            float4 v = (gn < n)
                ? *reinterpret_cast<const float4*>(&A[(size_t)gn * 64 + k0 + kp])
                : make_float4(0.f, 0.f, 0.f, 0.f);
            As[kp][node] = v.x; As[kp + 1][node] = v.y;
            As[kp + 2][node] = v.z; As[kp + 3][node] = v.w;
        }
        __syncthreads();
        #pragma unroll
        for (int kk = 0; kk < 16; kk++) {
            float a = As[kk][tid];
            #pragma unroll
            for (int c = 0; c < 10; c++) acc[c] += a * Ws[k0 + kk][c];
        }
        __syncthreads();
    }
    int gn = n0 + tid;
    if (gn < n) {
        #pragma unroll
        for (int c = 0; c < 10; c++) C[(size_t)gn * 10 + c] = acc[c];
    }
}

// ---------------- propagation, 64 channels, fp16 gathers: warp per node ----------------
__global__ void prop64(const __half* __restrict__ Hin, float* __restrict__ Hout,
                       const float* __restrict__ bias, int n, int do_relu) {
    int gtid = blockIdx.x * blockDim.x + threadIdx.x;
    int v = gtid >> 5;
    int lane = threadIdx.x & 31;
    int wl = threadIdx.x >> 5;
    __shared__ int2 s_e[8][32];
    if (v >= n) return;

    float dv = g_dinv[v];
    float selfn = dv * dv;
    float2 xv = __half22float2(reinterpret_cast<const __half2*>(Hin + (size_t)v * 64)[lane]);
    float2 acc = make_float2(selfn * xv.x, selfn * xv.y);

    int e0 = g_rowptr[v], e1 = g_rowptr[v + 1];
    for (int base = e0; base < e1; base += 32) {
        int ne = min(32, e1 - base);
        if (lane < ne) s_e[wl][lane] = g_edge[base + lane];
        __syncwarp();
        #pragma unroll 4
        for (int j = 0; j < ne; j++) {
            int2 e = s_e[wl][j];
            float nm = __int_as_float(e.y);
            float2 hh = __half22float2(
                reinterpret_cast<const __half2*>(Hin + (size_t)e.x * 64)[lane]);
            acc.x += nm * hh.x;
            acc.y += nm * hh.y;
        }
        __syncwarp();
    }
    float2 b = reinterpret_cast<const float2*>(bias)[lane];
    acc.x += b.x; acc.y += b.y;
    if (do_relu) {
        acc.x = fmaxf(acc.x, 0.f);
        acc.y = fmaxf(acc.y, 0.f);
    }
    reinterpret_cast<float2*>(Hout + (size_t)v * 64)[lane] = acc;
}

// ---------------- propagation 10ch + fused mean-pool accumulation ----------------
__global__ void prop10_pool(const float* __restrict__ Hin, const float* __restrict__ bias,
                            const int* __restrict__ batch, int n) {
    int gtid = blockIdx.x * blockDim.x + threadIdx.x;
    int v = gtid >> 5;
    int lane = threadIdx.x & 31;
    int wl = threadIdx.x >> 5;
    __shared__ int2 s_e[8][32];
    if (v >= n) return;

    float dv = g_dinv[v];
    float selfn = dv * dv;
    float acc = 0.f;
    if (lane < NUM_CLASSES) acc = selfn * Hin[(size_t)v * 10 + lane];

    int e0 = g_rowptr[v], e1 = g_rowptr[v + 1];
    for (int base = e0; base < e1; base += 32) {
        int ne = min(32, e1 - base);
        if (lane < ne) s_e[wl][lane] = g_edge[base + lane];
        __syncwarp();
        for (int j = 0; j < ne; j++) {
            int2 e = s_e[wl][j];
            float nm = __int_as_float(e.y);
            if (lane < NUM_CLASSES)
                acc += nm * Hin[(size_t)e.x * 10 + lane];
        }
        __syncwarp();
    }
    int g = batch[v];
    if (lane < NUM_CLASSES)
        atomicAdd(&g_pool[g * 10 + lane], acc + bias[lane]);
    if (lane == NUM_CLASSES)
        atomicAdd(&g_pcnt[g], 1.f);
}

// ---------------- final mean + log_softmax ----------------
__global__ void final_kernel(float* __restrict__ out) {
    int g = threadIdx.x;
    if (g >= NUM_GRAPHS) return;
    float inv = 1.f / fmaxf(g_pcnt[g], 1.f);
    float v[NUM_CLASSES];
    float m = -1e30f;
    #pragma unroll
    for (int c = 0; c < NUM_CLASSES; c++) {
        v[c] = g_pool[g * 10 + c] * inv;
        m = fmaxf(m, v[c]);
    }
    float ssum = 0.f;
    #pragma unroll
    for (int c = 0; c < NUM_CLASSES; c++) ssum += expf(v[c] - m);
    float lse = m + logf(ssum);
    #pragma unroll
    for (int c = 0; c < NUM_CLASSES; c++) out[g * 10 + c] = v[c] - lse;
}

// ---------------- launch ----------------
extern "C" void kernel_launch(void* const* d_in, const int* in_sizes, int n_in,
                              void* d_out, int out_size) {
    const float* x   = (const float*)d_in[0];
    const int*   ei  = (const int*)d_in[1];
    const int*   bat = (const int*)d_in[2];
    const float* W1  = (const float*)d_in[3];
    const float* b1  = (const float*)d_in[4];
    const float* W2  = (const float*)d_in[5];
    const float* b2  = (const float*)d_in[6];
    const float* W3  = (const float*)d_in[7];
    const float* b3  = (const float*)d_in[8];
    float* out = (float*)d_out;

    __half* th = nullptr; float* h = nullptr; float* t10 = nullptr;
    void *p_cnt, *p_fill, *p_pool, *p_pcnt;
    cudaGetSymbolAddress((void**)&th, g_th);
    cudaGetSymbolAddress((void**)&h, g_h);
    cudaGetSymbolAddress((void**)&t10, g_t10);
    cudaGetSymbolAddress(&p_cnt, g_cnt);
    cudaGetSymbolAddress(&p_fill, g_fill);
    cudaGetSymbolAddress(&p_pool, g_pool);
    cudaGetSymbolAddress(&p_pcnt, g_pcnt);

    static cudaStream_t s2 = nullptr;
    static cudaEvent_t evFork = nullptr, evJoin = nullptr;
    if (s2 == nullptr) {
        cudaStreamCreateWithFlags(&s2, cudaStreamNonBlocking);
        cudaEventCreateWithFlags(&evFork, cudaEventDisableTiming);
        cudaEventCreateWithFlags(&evJoin, cudaEventDisableTiming);
    }

    const int TB = 256;
    int nblk  = (N_NODES + TB - 1) / TB;
    int eblk  = (N_EDGES + TB - 1) / TB;
    int wblk  = (N_NODES * 32 + TB - 1) / TB;
    int gblk  = (N_NODES + 127) / 128;
    const size_t GSM = 8 * 32 * 36 * sizeof(float);   // 36864 bytes

    // pool zeroing on main stream (needed only at the end)
    cudaMemsetAsync(p_pool, 0, NUM_GRAPHS * NUM_CLASSES * sizeof(float), 0);
    cudaMemsetAsync(p_pcnt, 0, NUM_GRAPHS * sizeof(float), 0);

    // ---- fork: CSR preprocessing on s2, GEMM-1 on main ----
    cudaEventRecord(evFork, 0);
    cudaStreamWaitEvent(s2, evFork, 0);

    cudaMemsetAsync(p_cnt,  0, N_NODES * sizeof(int), s2);
    cudaMemsetAsync(p_fill, 0, N_NODES * sizeof(int), s2);
    count_kernel<<<eblk, TB, 0, s2>>>(ei);
    blocksum_dinv<<<SCAN_NBLK, SCAN_BS, 0, s2>>>();
    scan_partials<<<1, 128, 0, s2>>>();
    write_rowptr<<<SCAN_NBLK, SCAN_BS, 0, s2>>>();
    scatter_kernel<<<eblk, TB, 0, s2>>>(ei);
    cudaEventRecord(evJoin, s2);

    // main stream: x @ W1 -> th (half)
    gemm64_tc<IN_CH><<<gblk, TB, GSM>>>(x, W1, th, N_NODES);

    // ---- join ----
    cudaStreamWaitEvent(0, evJoin, 0);

    // layer 1
    prop64<<<wblk, TB>>>(th, h, b1, N_NODES, 1);
    // layer 2
    gemm64_tc<HID><<<gblk, TB, GSM>>>(h, W2, th, N_NODES);
    prop64<<<wblk, TB>>>(th, h, b2, N_NODES, 1);
    // layer 3
    gemm_out10<<<nblk, TB>>>(h, W3, t10, N_NODES);
    prop10_pool<<<wblk, TB>>>(t10, b3, bat, N_NODES);

    final_kernel<<<1, 64>>>(out);
}